// round 2
// baseline (speedup 1.0000x reference)
#include <cuda_runtime.h>

// Shapes fixed by the problem: [B=4, C=32, H=1024, W=1024] fp32 -> [B,H,W] fp32
#define CCH 32
#define HH  1024
#define WW  1024
#define RAD 25   // kernel_radius = W // 40 = 25 (window = 51)
#define RPB 8    // rows per block in kernel A

// 16 MB scratch for channel-summed + box-w'd intermediate
__device__ float g_scratch[4 * HH * WW];

// ---------------------------------------------------------------------------
// Kernel A: per (b, 8-row tile) — gradient magnitude, channel sum, box-w.
// 256 threads; each thread owns 4 consecutive w (float4) for all 8 rows.
// The "top" neighbor row is kept in registers across the inner row loop, so
// each input row is loaded (R+1)/R = 1.125x instead of 2x.
// ---------------------------------------------------------------------------
__global__ __launch_bounds__(256, 2) void grad_boxw_kernel(const float* __restrict__ x) {
    const int h0   = blockIdx.x * RPB;
    const int b    = blockIdx.y;
    const int tid  = threadIdx.x;
    const int lane = tid & 31;
    const int wid  = tid >> 5;
    const int w0   = tid << 2;

    const float* xb = x + (size_t)b * CCH * HH * WW;

    float acc[RPB][4];
    #pragma unroll
    for (int r = 0; r < RPB; ++r)
        acc[r][0] = acc[r][1] = acc[r][2] = acc[r][3] = 0.f;

    for (int c = 0; c < CCH; ++c) {
        const float* base = xb + (size_t)c * HH * WW;

        float4 prev;
        if (h0 > 0) prev = *reinterpret_cast<const float4*>(base + (size_t)(h0 - 1) * WW + w0);
        else        prev = make_float4(0.f, 0.f, 0.f, 0.f);

        #pragma unroll
        for (int r = 0; r < RPB; ++r) {
            const float* row = base + (size_t)(h0 + r) * WW;
            float4 cur = *reinterpret_cast<const float4*>(row + w0);

            float left = __shfl_up_sync(0xffffffffu, cur.w, 1);
            if (lane == 0) left = (w0 > 0) ? row[w0 - 1] : 0.f;

            float dx0 = left  - cur.x;
            float dx1 = cur.x - cur.y;
            float dx2 = cur.y - cur.z;
            float dx3 = cur.z - cur.w;
            float dy0 = prev.x - cur.x;
            float dy1 = prev.y - cur.y;
            float dy2 = prev.z - cur.z;
            float dy3 = prev.w - cur.w;

            float s0 = dx0 * dx0 + dy0 * dy0;
            float s1 = dx1 * dx1 + dy1 * dy1;
            float s2 = dx2 * dx2 + dy2 * dy2;
            float s3 = dx3 * dx3 + dy3 * dy3;

            acc[r][0] += (s0 > 0.f) ? s0 * rsqrtf(s0) : 0.f;
            acc[r][1] += (s1 > 0.f) ? s1 * rsqrtf(s1) : 0.f;
            acc[r][2] += (s2 > 0.f) ? s2 * rsqrtf(s2) : 0.f;
            acc[r][3] += (s3 > 0.f) ? s3 * rsqrtf(s3) : 0.f;

            prev = cur;
        }
    }

    // ---- per-row block prefix sum + box-w, 8 rows sequentially ----
    __shared__ float S[WW + 1];
    __shared__ float wsum[8];

    float* gb = g_scratch + (size_t)b * HH * WW;

    #pragma unroll 1
    for (int r = 0; r < RPB; ++r) {
        float p0 = acc[r][0];
        float p1 = p0 + acc[r][1];
        float p2 = p1 + acc[r][2];
        float p3 = p2 + acc[r][3];
        float t  = p3;

        // inclusive warp scan of t
        float sc = t;
        #pragma unroll
        for (int o = 1; o < 32; o <<= 1) {
            float v = __shfl_up_sync(0xffffffffu, sc, o);
            if (lane >= o) sc += v;
        }
        if (lane == 31) wsum[wid] = sc;
        __syncthreads();
        if (wid == 0) {
            float wv = (lane < 8) ? wsum[lane] : 0.f;
            float ws = wv;
            #pragma unroll
            for (int o = 1; o < 8; o <<= 1) {
                float v = __shfl_up_sync(0xffffffffu, ws, o);
                if (lane >= o) ws += v;
            }
            if (lane < 8) wsum[lane] = ws - wv;  // exclusive warp offsets
        }
        __syncthreads();

        float bofs = wsum[wid] + (sc - t);  // exclusive offset for this thread
        if (tid == 0) S[0] = 0.f;
        S[w0 + 1] = bofs + p0;
        S[w0 + 2] = bofs + p1;
        S[w0 + 3] = bofs + p2;
        S[w0 + 4] = bofs + p3;
        __syncthreads();

        float* grow = gb + (size_t)(h0 + r) * WW;
        #pragma unroll
        for (int i = 0; i < 4; ++i) {
            int w  = w0 + i;
            int lo = max(0, w - RAD);
            int hi = min(WW - 1, w + RAD);
            grow[w] = S[hi + 1] - S[lo];
        }
        __syncthreads();   // protect S/wsum reuse in next iteration
    }
}

// ---------------------------------------------------------------------------
// Kernel B: box filter along h (sliding window, float4 columns, coalesced)
// grid = (1, HH/HT, B), block = 256 threads; thread owns 4 adjacent columns.
// ---------------------------------------------------------------------------
#define HT 16
#define W4 (WW / 4)
__global__ __launch_bounds__(256) void boxh_kernel(float* __restrict__ out) {
    const int c4 = blockIdx.x * 256 + threadIdx.x;   // float4 column index
    const int h0 = blockIdx.y * HT;
    const int b  = blockIdx.z;

    const float4* gp = reinterpret_cast<const float4*>(g_scratch + (size_t)b * HH * WW) + c4;
    float4*       op = reinterpret_cast<float4*>(out + (size_t)b * HH * WW) + c4;

    float4 s = make_float4(0.f, 0.f, 0.f, 0.f);
    const int jlo = max(0, h0 - RAD);
    const int jhi = min(HH - 1, h0 + RAD);
    for (int j = jlo; j <= jhi; ++j) {
        float4 v = gp[(size_t)j * W4];
        s.x += v.x; s.y += v.y; s.z += v.z; s.w += v.w;
    }

    #pragma unroll
    for (int i = 0; i < HT; ++i) {
        const int h = h0 + i;
        op[(size_t)h * W4] = s;
        const int add = h + RAD + 1;
        const int sub = h - RAD;
        if (add < HH) {
            float4 v = gp[(size_t)add * W4];
            s.x += v.x; s.y += v.y; s.z += v.z; s.w += v.w;
        }
        if (sub >= 0) {
            float4 v = gp[(size_t)sub * W4];
            s.x -= v.x; s.y -= v.y; s.z -= v.z; s.w -= v.w;
        }
    }
}

// ---------------------------------------------------------------------------

extern "C" void kernel_launch(void* const* d_in, const int* in_sizes, int n_in,
                              void* d_out, int out_size) {
    const float* x = (const float*)d_in[0];
    float* out = (float*)d_out;

    const int n = in_sizes[0];
    const int B = n / (CCH * HH * WW);   // 4

    dim3 gridA(HH / RPB, B);
    grad_boxw_kernel<<<gridA, 256>>>(x);

    dim3 gridB(W4 / 256, HH / HT, B);
    boxh_kernel<<<gridB, 256>>>(out);
}